// round 13
// baseline (speedup 1.0000x reference)
#include <cuda_runtime.h>

// SelfAttention: B=2, L=2048, E=512, H=8, D=64
//   q/k/v = X @ W.T + b            (3 GEMMs 4096x512x512, head-major out)
//   S = q k^T; mask==0 -> -1e20; softmax(S/sqrt(512)); O = P v   (flash-fused)
//   out = O @ Wo.T + bo            (GEMM 4096x512x512)
// All fp32; inner loops use Blackwell f32x2 packed FMA (2x FFMA throughput).

#define cB 2
#define cL 2048
#define cE 512
#define cH 8
#define cD 64

__device__ float g_Q[cB * cH * cL * cD];
__device__ float g_K[cB * cH * cL * cD];
__device__ float g_V[cB * cH * cL * cD];
__device__ float g_O[cB * cL * cE];

__device__ __forceinline__ void fma2(unsigned long long& d,
                                     unsigned long long a,
                                     unsigned long long b) {
    asm("fma.rn.f32x2 %0, %1, %2, %0;" : "+l"(d) : "l"(a), "l"(b));
}
__device__ __forceinline__ void mul2(unsigned long long& d, unsigned long long a) {
    asm("mul.rn.f32x2 %0, %0, %1;" : "+l"(d) : "l"(a));
}
__device__ __forceinline__ unsigned long long pk2(float lo, float hi) {
    unsigned long long r;
    asm("mov.b64 %0, {%1, %2};" : "=l"(r) : "f"(lo), "f"(hi));
    return r;
}
__device__ __forceinline__ float2 upk2(unsigned long long v) {
    float2 f;
    asm("mov.b64 {%0, %1}, %2;" : "=f"(f.x), "=f"(f.y) : "l"(v));
    return f;
}

// ---------------------------------------------------------------------------
// GEMM: Y[m,n] = sum_k X[m,k] * W[n,k] + bias[n]
// M=4096, N=512, K=512. Block tile 128x64, BK=16, 256 threads, 8x4 micro-tile.
// which: 0/1/2 -> write head-major [B,H,L,D] into g_Q/g_K/g_V; 3 -> plain into
// dst, with X read from g_O.
// ---------------------------------------------------------------------------
__global__ __launch_bounds__(256, 2)
void gemm_kernel(const float* __restrict__ X, const float* __restrict__ W,
                 const float* __restrict__ bias, float* __restrict__ dst,
                 const int which)
{
    __shared__ __align__(16) float As[128][20];  // [m][k], pad->20 (odd quads)
    __shared__ __align__(16) float Bs[64][20];   // [n][k]
    const float* __restrict__ Xp = (which == 3) ? g_O : X;

    const int tid = threadIdx.x;
    const int ty = tid >> 4;           // 0..15 (row group)
    const int tx = tid & 15;           // 0..15 (col lane)
    const int m0 = blockIdx.y * 128;
    const int n0 = blockIdx.x * 64;

    unsigned long long acc[8][4];      // 8 rows x 4 cols, f32x2 pairs over k
#pragma unroll
    for (int i = 0; i < 8; i++)
#pragma unroll
        for (int j = 0; j < 4; j++) acc[i][j] = 0ull;

    for (int kb = 0; kb < cE; kb += 16) {
#pragma unroll
        for (int it = 0; it < 2; it++) {
            int idx = tid + it * 256;
            int row = idx >> 2, q = idx & 3;
            *(float4*)&As[row][q * 4] =
                *(const float4*)(Xp + (size_t)(m0 + row) * cE + kb + q * 4);
        }
        {
            int row = tid >> 2, q = tid & 3;
            *(float4*)&Bs[row][q * 4] =
                *(const float4*)(W + (size_t)(n0 + row) * cE + kb + q * 4);
        }
        __syncthreads();
#pragma unroll
        for (int k4 = 0; k4 < 4; k4++) {
            ulonglong2 b2[4];
#pragma unroll
            for (int j = 0; j < 4; j++)
                b2[j] = *(const ulonglong2*)&Bs[j * 16 + tx][k4 * 4];
#pragma unroll
            for (int i = 0; i < 8; i++) {
                ulonglong2 a2 = *(const ulonglong2*)&As[ty * 8 + i][k4 * 4];
#pragma unroll
                for (int j = 0; j < 4; j++) {
                    fma2(acc[i][j], a2.x, b2[j].x);
                    fma2(acc[i][j], a2.y, b2[j].y);
                }
            }
        }
        __syncthreads();
    }

    float bj[4];
#pragma unroll
    for (int j = 0; j < 4; j++) bj[j] = bias[n0 + j * 16 + tx];

    if (which == 3) {
#pragma unroll
        for (int i = 0; i < 8; i++) {
            int m = m0 + ty * 8 + i;
#pragma unroll
            for (int j = 0; j < 4; j++) {
                float2 p = upk2(acc[i][j]);
                dst[(size_t)m * cE + n0 + j * 16 + tx] = p.x + p.y + bj[j];
            }
        }
    } else {
        float* G = (which == 0) ? g_Q : (which == 1) ? g_K : g_V;
        const int h = n0 >> 6;  // BN=64 == D, one head per block column
#pragma unroll
        for (int i = 0; i < 8; i++) {
            int m = m0 + ty * 8 + i;
            int b = m >> 11;            // /L
            int l = m & (cL - 1);
            size_t base = (((size_t)(b * cH + h)) * cL + l) * cD;
#pragma unroll
            for (int j = 0; j < 4; j++) {
                float2 p = upk2(acc[i][j]);
                G[base + j * 16 + tx] = p.x + p.y + bj[j];
            }
        }
    }
}

// ---------------------------------------------------------------------------
// Flash attention, fp32. One block = one (b,h) and a 64-row q-tile.
// 256 threads (16x16). S tile rows r=i*16+ty, cols c=j*16+tx (strided mapping
// -> conflict-free SMEM reads). O tile rows r=i*16+ty, cols d=tx*4+j (float4).
// ---------------------------------------------------------------------------
#define SROW 68
#define SMEM_ATTN (4 * 64 * SROW * 4)

__global__ __launch_bounds__(256, 2)
void attn_kernel(const int* __restrict__ mask)
{
    extern __shared__ float sm[];
    float* Qs = sm;                    // [64][68]
    float* Ks = sm + 64 * SROW;
    float* Vs = sm + 2 * 64 * SROW;
    float* Ps = sm + 3 * 64 * SROW;

    const int tid = threadIdx.x;
    const int ty = tid >> 4;
    const int tx = tid & 15;
    const int q0 = blockIdx.x * 64;
    const int bh = blockIdx.y;         // b*H + h
    const int b = bh >> 3;
    const int h = bh & 7;
    const float* gq = g_Q + (size_t)bh * cL * cD;
    const float* gk = g_K + (size_t)bh * cL * cD;
    const float* gv = g_V + (size_t)bh * cL * cD;
    const size_t mbase = (size_t)b * cL * cL;

#pragma unroll
    for (int it = 0; it < 4; it++) {
        int idx = tid + it * 256;
        int row = idx >> 4, q = idx & 15;
        *(float4*)&Qs[row * SROW + q * 4] =
            *(const float4*)(gq + (size_t)(q0 + row) * cD + q * 4);
    }

    unsigned long long accO[4][2];
    float mrow[4], lrow[4];
#pragma unroll
    for (int i = 0; i < 4; i++) {
        accO[i][0] = 0ull; accO[i][1] = 0ull;
        mrow[i] = -1e30f;
        lrow[i] = 0.f;
    }
    const float rs = 0.04419417382415922f;       // 1/sqrt(512)
    const float MASKED = -4.4194173824159216e18f; // -1e20/sqrt(512)

    for (int kt = 0; kt < cL / 64; kt++) {
        const int k0 = kt * 64;
        __syncthreads();   // prior iteration's reads of Ks/Vs/Ps complete
#pragma unroll
        for (int it = 0; it < 4; it++) {
            int idx = tid + it * 256;
            int row = idx >> 4, q = idx & 15;
            *(float4*)&Ks[row * SROW + q * 4] =
                *(const float4*)(gk + (size_t)(k0 + row) * cD + q * 4);
            *(float4*)&Vs[row * SROW + q * 4] =
                *(const float4*)(gv + (size_t)(k0 + row) * cD + q * 4);
        }
        // Prefetch mask for this tile (latency hidden under S-GEMM)
        int mv[4][4];
#pragma unroll
        for (int i = 0; i < 4; i++)
#pragma unroll
            for (int j = 0; j < 4; j++)
                mv[i][j] = mask[mbase + (size_t)(q0 + i * 16 + ty) * cL +
                                k0 + j * 16 + tx];
        __syncthreads();

        // S = Q @ K^T  (f32x2 pairs over d, reduce pair at the end)
        unsigned long long accS[4][4];
#pragma unroll
        for (int i = 0; i < 4; i++)
#pragma unroll
            for (int j = 0; j < 4; j++) accS[i][j] = 0ull;

#pragma unroll 4
        for (int d4 = 0; d4 < 16; d4++) {
            ulonglong2 b2[4];
#pragma unroll
            for (int j = 0; j < 4; j++)
                b2[j] = *(const ulonglong2*)&Ks[(j * 16 + tx) * SROW + d4 * 4];
#pragma unroll
            for (int i = 0; i < 4; i++) {
                ulonglong2 a2 =
                    *(const ulonglong2*)&Qs[(i * 16 + ty) * SROW + d4 * 4];
#pragma unroll
                for (int j = 0; j < 4; j++) {
                    fma2(accS[i][j], a2.x, b2[j].x);
                    fma2(accS[i][j], a2.y, b2[j].y);
                }
            }
        }

        // mask + scale + online softmax (row = 16 lanes sharing ty)
#pragma unroll
        for (int i = 0; i < 4; i++) {
            const int r = i * 16 + ty;
            float s[4];
#pragma unroll
            for (int j = 0; j < 4; j++) {
                float2 p = upk2(accS[i][j]);
                s[j] = (mv[i][j] != 0) ? (p.x + p.y) * rs : MASKED;
            }
            float mx = fmaxf(fmaxf(s[0], s[1]), fmaxf(s[2], s[3]));
#pragma unroll
            for (int o = 8; o > 0; o >>= 1)
                mx = fmaxf(mx, __shfl_xor_sync(0xffffffffu, mx, o));
            const float mn = fmaxf(mrow[i], mx);
            const float fac = __expf(mrow[i] - mn);
            mrow[i] = mn;
            float rsum = 0.f;
#pragma unroll
            for (int j = 0; j < 4; j++) {
                float pv = __expf(s[j] - mn);
                Ps[r * SROW + j * 16 + tx] = pv;
                rsum += pv;
            }
#pragma unroll
            for (int o = 8; o > 0; o >>= 1)
                rsum += __shfl_xor_sync(0xffffffffu, rsum, o);
            lrow[i] = lrow[i] * fac + rsum;
            unsigned long long f2 = pk2(fac, fac);
            mul2(accO[i][0], f2);
            mul2(accO[i][1], f2);
        }
        __syncthreads();

        // O += P @ V
#pragma unroll 8
        for (int c = 0; c < 64; c++) {
            ulonglong2 v2 = *(const ulonglong2*)&Vs[c * SROW + tx * 4];
#pragma unroll
            for (int i = 0; i < 4; i++) {
                float pv = Ps[(i * 16 + ty) * SROW + c];
                unsigned long long p2 = pk2(pv, pv);
                fma2(accO[i][0], p2, v2.x);
                fma2(accO[i][1], p2, v2.y);
            }
        }
    }

    // epilogue: normalize, write interleaved [B, L, E] (E idx = h*D + d)
#pragma unroll
    for (int i = 0; i < 4; i++) {
        const float inv = 1.0f / lrow[i];
        float2 o0 = upk2(accO[i][0]);
        float2 o1 = upk2(accO[i][1]);
        float4 o = make_float4(o0.x * inv, o0.y * inv, o1.x * inv, o1.y * inv);
        const int row = q0 + i * 16 + ty;
        *(float4*)(g_O + ((size_t)(b * cL + row)) * cE + h * cD + tx * 4) = o;
    }
}

// ---------------------------------------------------------------------------
extern "C" void kernel_launch(void* const* d_in, const int* in_sizes, int n_in,
                              void* d_out, int out_size)
{
    const float* values = (const float*)d_in[0];
    const float* keys   = (const float*)d_in[1];
    const float* query  = (const float*)d_in[2];
    const int*   mask   = (const int*)d_in[3];
    const float* Wv = (const float*)d_in[4];
    const float* bv = (const float*)d_in[5];
    const float* Wk = (const float*)d_in[6];
    const float* bk = (const float*)d_in[7];
    const float* Wq = (const float*)d_in[8];
    const float* bq = (const float*)d_in[9];
    const float* Wo = (const float*)d_in[10];
    const float* bo = (const float*)d_in[11];
    float* out = (float*)d_out;

    const dim3 gg(cE / 64, (cB * cL) / 128);  // (8, 32)
    gemm_kernel<<<gg, 256>>>(query,  Wq, bq, nullptr, 0);  // -> g_Q
    gemm_kernel<<<gg, 256>>>(keys,   Wk, bk, nullptr, 1);  // -> g_K
    gemm_kernel<<<gg, 256>>>(values, Wv, bv, nullptr, 2);  // -> g_V

    cudaFuncSetAttribute(attn_kernel,
                         cudaFuncAttributeMaxDynamicSharedMemorySize,
                         SMEM_ATTN);
    attn_kernel<<<dim3(cL / 64, cB * cH), 256, SMEM_ATTN>>>(mask);

    gemm_kernel<<<gg, 256>>>(nullptr, Wo, bo, out, 3);     // g_O -> out
}

// round 16
// speedup vs baseline: 1.1642x; 1.1642x over previous
#include <cuda_runtime.h>
#include <cstdint>

#define cB 2
#define cL 2048
#define cE 512
#define cH 8
#define cD 64

__device__ float g_Q[cB * cH * cL * cD];
__device__ float g_K[cB * cH * cL * cD];
__device__ float g_V[cB * cH * cL * cD];
__device__ float g_O[cB * cL * cE];

// ---------------- helpers ----------------
__device__ __forceinline__ void fma2(unsigned long long& d, unsigned long long a,
                                     unsigned long long b) {
    asm("fma.rn.f32x2 %0, %1, %2, %0;" : "+l"(d) : "l"(a), "l"(b));
}
__device__ __forceinline__ void mul2(unsigned long long& d, unsigned long long a) {
    asm("mul.rn.f32x2 %0, %0, %1;" : "+l"(d) : "l"(a));
}
__device__ __forceinline__ unsigned long long pk2(float lo, float hi) {
    unsigned long long r;
    asm("mov.b64 %0, {%1, %2};" : "=l"(r) : "f"(lo), "f"(hi));
    return r;
}
__device__ __forceinline__ float2 upk2(unsigned long long v) {
    float2 f;
    asm("mov.b64 {%0, %1}, %2;" : "=f"(f.x), "=f"(f.y) : "l"(v));
    return f;
}
__device__ __forceinline__ uint32_t smem_u32(const void* p) {
    return (uint32_t)__cvta_generic_to_shared(p);
}
__device__ __forceinline__ void cp16(uint32_t dst, const void* src) {
    asm volatile("cp.async.cg.shared.global [%0], [%1], 16;" :: "r"(dst), "l"(src)
                 : "memory");
}
__device__ __forceinline__ void cp_commit() {
    asm volatile("cp.async.commit_group;" ::: "memory");
}
__device__ __forceinline__ void cp_wait0() {
    asm volatile("cp.async.wait_group 0;" ::: "memory");
}
__device__ __forceinline__ void cp_wait1() {
    asm volatile("cp.async.wait_group 1;" ::: "memory");
}
__device__ __forceinline__ float tf32_rn(float x) {
    float y;
    asm("cvt.rna.tf32.f32 %0, %1;" : "=f"(y) : "f"(x));
    return y;
}
__device__ __forceinline__ void ldmx4(uint32_t* r, uint32_t a) {
    asm volatile("ldmatrix.sync.aligned.m8n8.x4.shared.b16 {%0,%1,%2,%3}, [%4];"
                 : "=r"(r[0]), "=r"(r[1]), "=r"(r[2]), "=r"(r[3]) : "r"(a));
}
__device__ __forceinline__ void mma8(float* c, const uint32_t* a, uint32_t b0,
                                     uint32_t b1) {
    asm volatile(
        "mma.sync.aligned.m16n8k8.row.col.f32.tf32.tf32.f32 "
        "{%0,%1,%2,%3}, {%4,%5,%6,%7}, {%8,%9}, {%0,%1,%2,%3};"
        : "+f"(c[0]), "+f"(c[1]), "+f"(c[2]), "+f"(c[3])
        : "r"(a[0]), "r"(a[1]), "r"(a[2]), "r"(a[3]), "r"(b0), "r"(b1));
}
__device__ __forceinline__ void tf32split(uint32_t raw, uint32_t& hi, uint32_t& lo) {
    float f = __uint_as_float(raw);
    float h = tf32_rn(f);
    float l = tf32_rn(f - h);
    hi = __float_as_uint(h);
    lo = __float_as_uint(l);
}

// ---------------------------------------------------------------------------
// GEMM: Y[m,n] = sum_k X[m,k] W[n,k] + bias[n] via mma.sync tf32, 3xTF32 split.
// BM=128, BN=64, BK=32; 8 warps (4m x 2n), warp tile 32x32; cp.async dbl-buf.
// which 0/1/2: head-major scatter to g_Q/g_K/g_V; 3: plain to dst (X = g_O).
// ---------------------------------------------------------------------------
#define GPAD 36
#define GA_SZ (128 * GPAD)
#define GB_SZ (64 * GPAD)
#define GBUF (GA_SZ + GB_SZ)
#define GSMEM (2 * GBUF * 4)   // 55,296 B

__global__ __launch_bounds__(256, 2)
void gemm_tc(const float* __restrict__ Xin, const float* __restrict__ W,
             const float* __restrict__ bias, float* __restrict__ dst,
             const int which)
{
    extern __shared__ __align__(16) float gsm[];
    const uint32_t sb = smem_u32(gsm);
    const int tid = threadIdx.x;
    const int lane = tid & 31, warp = tid >> 5;
    const int warpM = warp >> 1, warpN = warp & 1;
    const int m0 = blockIdx.x * 128, n0 = blockIdx.y * 64;
    const float* __restrict__ X = (which == 3) ? g_O : Xin;

    // ldmatrix per-lane addressing (bytes, buffer-relative)
    const int g = lane >> 3, r8 = lane & 7;
    const int row_in = (g & 1) * 8 + r8;
    const int coladd = (g >> 1) * 4;
    const uint32_t a_lm =
        (uint32_t)(((warpM * 32 + row_in) * GPAD + coladd) * 4);
    const uint32_t b_lm =
        (uint32_t)((GA_SZ + (warpN * 32 + row_in) * GPAD + coladd) * 4);

    float acc[2][4][4];
#pragma unroll
    for (int mt = 0; mt < 2; mt++)
#pragma unroll
        for (int nt = 0; nt < 4; nt++)
#pragma unroll
            for (int r = 0; r < 4; r++) acc[mt][nt][r] = 0.f;

    // chunk fill via cp.async
    const int frow = tid >> 3, fq = tid & 7;
    auto fill = [&](int c) {
        const int kb = c * 32;
        const uint32_t bufb = sb + (uint32_t)((c & 1) * GBUF * 4);
#pragma unroll
        for (int it = 0; it < 4; it++) {
            int row = frow + it * 32;
            cp16(bufb + (uint32_t)((row * GPAD + fq * 4) * 4),
                 X + (size_t)(m0 + row) * cE + kb + fq * 4);
        }
#pragma unroll
        for (int it = 0; it < 2; it++) {
            int row = frow + it * 32;
            cp16(bufb + (uint32_t)((GA_SZ + row * GPAD + fq * 4) * 4),
                 W + (size_t)(n0 + row) * cE + kb + fq * 4);
        }
        cp_commit();
    };

    fill(0);
    for (int c = 0; c < 16; ++c) {
        if (c + 1 < 16) { fill(c + 1); cp_wait1(); }
        else cp_wait0();
        __syncthreads();
        const uint32_t bufb = (uint32_t)((c & 1) * GBUF * 4);
#pragma unroll
        for (int kt = 0; kt < 4; kt++) {
            uint32_t araw[2][4], braw[2][4];
#pragma unroll
            for (int mt = 0; mt < 2; mt++)
                ldmx4(araw[mt], sb + bufb + a_lm +
                                (uint32_t)((mt * 16 * GPAD + kt * 8) * 4));
#pragma unroll
            for (int p = 0; p < 2; p++)
                ldmx4(braw[p], sb + bufb + b_lm +
                               (uint32_t)((p * 16 * GPAD + kt * 8) * 4));
            uint32_t ah[2][4], al[2][4], bh[2][4], bl[2][4];
#pragma unroll
            for (int mt = 0; mt < 2; mt++)
#pragma unroll
                for (int r = 0; r < 4; r++)
                    tf32split(araw[mt][r], ah[mt][r], al[mt][r]);
#pragma unroll
            for (int p = 0; p < 2; p++)
#pragma unroll
                for (int r = 0; r < 4; r++)
                    tf32split(braw[p][r], bh[p][r], bl[p][r]);
#pragma unroll
            for (int mt = 0; mt < 2; mt++)
#pragma unroll
                for (int nt = 0; nt < 4; nt++) {
                    const int p = nt >> 1, w = nt & 1;
                    float* cc = acc[mt][nt];
                    mma8(cc, ah[mt], bh[p][w], bh[p][2 + w]);
                    mma8(cc, ah[mt], bl[p][w], bl[p][2 + w]);
                    mma8(cc, al[mt], bh[p][w], bh[p][2 + w]);
                }
        }
        __syncthreads();
    }

    // epilogue
    const int h = blockIdx.y;   // cE/BN == H, n0 = h*64
#pragma unroll
    for (int mt = 0; mt < 2; mt++) {
        const int m = m0 + warpM * 32 + mt * 16 + (lane >> 2);
        const int b = m >> 11, l = m & (cL - 1);
#pragma unroll
        for (int nt = 0; nt < 4; nt++) {
            const int dcol = warpN * 32 + nt * 8 + (lane & 3) * 2;
            const float2 bb = *(const float2*)(bias + n0 + dcol);
            float2 lo = make_float2(acc[mt][nt][0] + bb.x, acc[mt][nt][1] + bb.y);
            float2 hi = make_float2(acc[mt][nt][2] + bb.x, acc[mt][nt][3] + bb.y);
            if (which == 3) {
                *(float2*)(dst + (size_t)m * cE + n0 + dcol) = lo;
                *(float2*)(dst + (size_t)(m + 8) * cE + n0 + dcol) = hi;
            } else {
                float* G = (which == 0) ? g_Q : (which == 1) ? g_K : g_V;
                float* gp = G + (((size_t)(b * cH + h)) * cL + l) * cD + dcol;
                *(float2*)gp = lo;
                *(float2*)(gp + 8 * cD) = hi;
            }
        }
    }
}

// ---------------------------------------------------------------------------
// Flash attention fp32: cp.async double-buffered K, V under S-GEMM, vec PV.
// ---------------------------------------------------------------------------
#define SROW 68
#define KTILE (64 * SROW)
#define SMEM_ATTN (5 * KTILE * 4)

__global__ __launch_bounds__(256, 2)
void attn_kernel(const int* __restrict__ mask)
{
    extern __shared__ __align__(16) float sm[];
    float* Qs = sm;
    float* Ks0 = sm + KTILE;
    float* Ks1 = sm + 2 * KTILE;
    float* Vs = sm + 3 * KTILE;
    float* Ps = sm + 4 * KTILE;
    const uint32_t sb = smem_u32(sm);
    const uint32_t ks_u0 = sb + KTILE * 4, ks_u1 = sb + 2 * KTILE * 4;
    const uint32_t vs_u = sb + 3 * KTILE * 4;

    const int tid = threadIdx.x, ty = tid >> 4, tx = tid & 15;
    const int q0 = blockIdx.x * 64, bh = blockIdx.y;
    const int b = bh >> 3, h = bh & 7;
    const float* gq = g_Q + (size_t)bh * cL * cD;
    const float* gk = g_K + (size_t)bh * cL * cD;
    const float* gv = g_V + (size_t)bh * cL * cD;
    const size_t mbase = (size_t)b * cL * cL;

#pragma unroll
    for (int it = 0; it < 4; it++) {
        int idx = tid + it * 256, row = idx >> 4, q = idx & 15;
        *(float4*)&Qs[row * SROW + q * 4] =
            *(const float4*)(gq + (size_t)(q0 + row) * cD + q * 4);
        cp16(ks_u0 + (uint32_t)(row * SROW + q * 4) * 4,
             gk + (size_t)row * cD + q * 4);
    }
    cp_commit();
    cp_wait0();
    __syncthreads();

    unsigned long long accO[4][2];
    float mrow[4], lrow[4];
#pragma unroll
    for (int i = 0; i < 4; i++) {
        accO[i][0] = 0ull; accO[i][1] = 0ull; mrow[i] = -1e30f; lrow[i] = 0.f;
    }
    const float rs = 0.04419417382415922f;          // 1/sqrt(512)
    const float MASKED = -4.4194173824159216e18f;   // -1e20/sqrt(512)

    for (int kt = 0; kt < cL / 64; kt++) {
        const int k0 = kt * 64;
        const float* Kc = (kt & 1) ? Ks1 : Ks0;
        const uint32_t knxt = (kt & 1) ? ks_u0 : ks_u1;
        __syncthreads();

#pragma unroll
        for (int it = 0; it < 4; it++) {            // V(kt) async
            int idx = tid + it * 256, row = idx >> 4, q = idx & 15;
            cp16(vs_u + (uint32_t)(row * SROW + q * 4) * 4,
                 gv + (size_t)(k0 + row) * cD + q * 4);
        }
        if (kt + 1 < cL / 64) {                     // K(kt+1) async
#pragma unroll
            for (int it = 0; it < 4; it++) {
                int idx = tid + it * 256, row = idx >> 4, q = idx & 15;
                cp16(knxt + (uint32_t)(row * SROW + q * 4) * 4,
                     gk + (size_t)(k0 + 64 + row) * cD + q * 4);
            }
        }
        cp_commit();

        int mv[4][4];
#pragma unroll
        for (int i = 0; i < 4; i++)
#pragma unroll
            for (int j = 0; j < 4; j++)
                mv[i][j] = mask[mbase + (size_t)(q0 + i * 16 + ty) * cL + k0 +
                                j * 16 + tx];

        unsigned long long accS[4][4];
#pragma unroll
        for (int i = 0; i < 4; i++)
#pragma unroll
            for (int j = 0; j < 4; j++) accS[i][j] = 0ull;
#pragma unroll 4
        for (int d4 = 0; d4 < 16; d4++) {
            ulonglong2 b2[4];
#pragma unroll
            for (int j = 0; j < 4; j++)
                b2[j] = *(const ulonglong2*)&Kc[(j * 16 + tx) * SROW + d4 * 4];
#pragma unroll
            for (int i = 0; i < 4; i++) {
                ulonglong2 a2 =
                    *(const ulonglong2*)&Qs[(i * 16 + ty) * SROW + d4 * 4];
#pragma unroll
                for (int j = 0; j < 4; j++) {
                    fma2(accS[i][j], a2.x, b2[j].x);
                    fma2(accS[i][j], a2.y, b2[j].y);
                }
            }
        }

#pragma unroll
        for (int i = 0; i < 4; i++) {
            const int r = i * 16 + ty;
            float s[4];
#pragma unroll
            for (int j = 0; j < 4; j++) {
                float2 p = upk2(accS[i][j]);
                s[j] = (mv[i][j] != 0) ? (p.x + p.y) * rs : MASKED;
            }
            float mx = fmaxf(fmaxf(s[0], s[1]), fmaxf(s[2], s[3]));
#pragma unroll
            for (int o = 8; o > 0; o >>= 1)
                mx = fmaxf(mx, __shfl_xor_sync(0xffffffffu, mx, o));
            const float mn = fmaxf(mrow[i], mx);
            const float fac = __expf(mrow[i] - mn);
            mrow[i] = mn;
            float rsum = 0.f;
#pragma unroll
            for (int j = 0; j < 4; j++) {
                float pv = __expf(s[j] - mn);
                Ps[r * SROW + j * 16 + tx] = pv;
                rsum += pv;
            }
#pragma unroll
            for (int o = 8; o > 0; o >>= 1)
                rsum += __shfl_xor_sync(0xffffffffu, rsum, o);
            lrow[i] = lrow[i] * fac + rsum;
            unsigned long long f2 = pk2(fac, fac);
            mul2(accO[i][0], f2);
            mul2(accO[i][1], f2);
        }
        cp_wait0();
        __syncthreads();

#pragma unroll 4
        for (int c4 = 0; c4 < 16; c4++) {
            const int c = c4 * 4;
            ulonglong2 v0 = *(const ulonglong2*)&Vs[(c + 0) * SROW + tx * 4];
            ulonglong2 v1 = *(const ulonglong2*)&Vs[(c + 1) * SROW + tx * 4];
            ulonglong2 v2 = *(const ulonglong2*)&Vs[(c + 2) * SROW + tx * 4];
            ulonglong2 v3 = *(const ulonglong2*)&Vs[(c + 3) * SROW + tx * 4];
#pragma unroll
            for (int i = 0; i < 4; i++) {
                float4 p = *(const float4*)&Ps[(i * 16 + ty) * SROW + c];
                unsigned long long p0 = pk2(p.x, p.x), p1 = pk2(p.y, p.y);
                unsigned long long p2 = pk2(p.z, p.z), p3 = pk2(p.w, p.w);
                fma2(accO[i][0], p0, v0.x); fma2(accO[i][1], p0, v0.y);
                fma2(accO[i][0], p1, v1.x); fma2(accO[i][1], p1, v1.y);
                fma2(accO[i][0], p2, v2.x); fma2(accO[i][1], p2, v2.y);
                fma2(accO[i][0], p3, v3.x); fma2(accO[i][1], p3, v3.y);
            }
        }
    }

#pragma unroll
    for (int i = 0; i < 4; i++) {
        const float inv = 1.0f / lrow[i];
        float2 o0 = upk2(accO[i][0]);
        float2 o1 = upk2(accO[i][1]);
        float4 o = make_float4(o0.x * inv, o0.y * inv, o1.x * inv, o1.y * inv);
        const int row = q0 + i * 16 + ty;
        *(float4*)(g_O + ((size_t)(b * cL + row)) * cE + h * cD + tx * 4) = o;
    }
}

// ---------------------------------------------------------------------------
extern "C" void kernel_launch(void* const* d_in, const int* in_sizes, int n_in,
                              void* d_out, int out_size)
{
    (void)in_sizes; (void)n_in; (void)out_size;
    const float* values = (const float*)d_in[0];
    const float* keys   = (const float*)d_in[1];
    const float* query  = (const float*)d_in[2];
    const int*   mask   = (const int*)d_in[3];
    const float* Wv = (const float*)d_in[4];
    const float* bv = (const float*)d_in[5];
    const float* Wk = (const float*)d_in[6];
    const float* bk = (const float*)d_in[7];
    const float* Wq = (const float*)d_in[8];
    const float* bq = (const float*)d_in[9];
    const float* Wo = (const float*)d_in[10];
    const float* bo = (const float*)d_in[11];
    float* out = (float*)d_out;

    cudaFuncSetAttribute(gemm_tc, cudaFuncAttributeMaxDynamicSharedMemorySize,
                         GSMEM);
    cudaFuncSetAttribute(attn_kernel, cudaFuncAttributeMaxDynamicSharedMemorySize,
                         SMEM_ATTN);

    const dim3 gg((cB * cL) / 128, cE / 64);   // (32, 8)
    gemm_tc<<<gg, 256, GSMEM>>>(query,  Wq, bq, nullptr, 0);
    gemm_tc<<<gg, 256, GSMEM>>>(keys,   Wk, bk, nullptr, 1);
    gemm_tc<<<gg, 256, GSMEM>>>(values, Wv, bv, nullptr, 2);

    attn_kernel<<<dim3(cL / 64, cB * cH), 256, SMEM_ATTN>>>(mask);

    gemm_tc<<<gg, 256, GSMEM>>>(nullptr, Wo, bo, out, 3);
}

// round 17
// speedup vs baseline: 1.9624x; 1.6855x over previous
#include <cuda_runtime.h>
#include <cstdint>

#define cB 2
#define cL 2048
#define cE 512
#define cH 8
#define cD 64

__device__ float g_Q[cB * cH * cL * cD];
__device__ float g_K[cB * cH * cL * cD];
__device__ float g_V[cB * cH * cL * cD];
__device__ float g_O[cB * cL * cE];

// ---------------- helpers ----------------
__device__ __forceinline__ uint32_t smem_u32(const void* p) {
    return (uint32_t)__cvta_generic_to_shared(p);
}
__device__ __forceinline__ void cp16(uint32_t dst, const void* src) {
    asm volatile("cp.async.cg.shared.global [%0], [%1], 16;" :: "r"(dst), "l"(src)
                 : "memory");
}
__device__ __forceinline__ void cp_commit() {
    asm volatile("cp.async.commit_group;" ::: "memory");
}
__device__ __forceinline__ void cp_wait0() {
    asm volatile("cp.async.wait_group 0;" ::: "memory");
}
__device__ __forceinline__ void cp_wait1() {
    asm volatile("cp.async.wait_group 1;" ::: "memory");
}
__device__ __forceinline__ float tf32_rn(float x) {
    float y;
    asm("cvt.rna.tf32.f32 %0, %1;" : "=f"(y) : "f"(x));
    return y;
}
__device__ __forceinline__ float ex2(float x) {
    float y;
    asm("ex2.approx.ftz.f32 %0, %1;" : "=f"(y) : "f"(x));
    return y;
}
__device__ __forceinline__ void ldmx4(uint32_t* r, uint32_t a) {
    asm volatile("ldmatrix.sync.aligned.m8n8.x4.shared.b16 {%0,%1,%2,%3}, [%4];"
                 : "=r"(r[0]), "=r"(r[1]), "=r"(r[2]), "=r"(r[3]) : "r"(a));
}
__device__ __forceinline__ void mma8(float* c, const uint32_t* a, uint32_t b0,
                                     uint32_t b1) {
    asm volatile(
        "mma.sync.aligned.m16n8k8.row.col.f32.tf32.tf32.f32 "
        "{%0,%1,%2,%3}, {%4,%5,%6,%7}, {%8,%9}, {%0,%1,%2,%3};"
        : "+f"(c[0]), "+f"(c[1]), "+f"(c[2]), "+f"(c[3])
        : "r"(a[0]), "r"(a[1]), "r"(a[2]), "r"(a[3]), "r"(b0), "r"(b1));
}
__device__ __forceinline__ void tf32split(uint32_t raw, uint32_t& hi, uint32_t& lo) {
    float f = __uint_as_float(raw);
    float h = tf32_rn(f);
    float l = tf32_rn(f - h);
    hi = __float_as_uint(h);
    lo = __float_as_uint(l);
}

// ---------------------------------------------------------------------------
// GEMM (unchanged from round 16): mma.sync tf32, 3xTF32 split.
// BM=128, BN=64, BK=32; 8 warps (4m x 2n), warp tile 32x32; cp.async dbl-buf.
// ---------------------------------------------------------------------------
#define GPAD 36
#define GA_SZ (128 * GPAD)
#define GB_SZ (64 * GPAD)
#define GBUF (GA_SZ + GB_SZ)
#define GSMEM (2 * GBUF * 4)

__global__ __launch_bounds__(256, 2)
void gemm_tc(const float* __restrict__ Xin, const float* __restrict__ W,
             const float* __restrict__ bias, float* __restrict__ dst,
             const int which)
{
    extern __shared__ __align__(16) float gsm[];
    const uint32_t sb = smem_u32(gsm);
    const int tid = threadIdx.x;
    const int lane = tid & 31, warp = tid >> 5;
    const int warpM = warp >> 1, warpN = warp & 1;
    const int m0 = blockIdx.x * 128, n0 = blockIdx.y * 64;
    const float* __restrict__ X = (which == 3) ? g_O : Xin;

    const int g = lane >> 3, r8 = lane & 7;
    const int row_in = (g & 1) * 8 + r8;
    const int coladd = (g >> 1) * 4;
    const uint32_t a_lm = (uint32_t)(((warpM * 32 + row_in) * GPAD + coladd) * 4);
    const uint32_t b_lm =
        (uint32_t)((GA_SZ + (warpN * 32 + row_in) * GPAD + coladd) * 4);

    float acc[2][4][4];
#pragma unroll
    for (int mt = 0; mt < 2; mt++)
#pragma unroll
        for (int nt = 0; nt < 4; nt++)
#pragma unroll
            for (int r = 0; r < 4; r++) acc[mt][nt][r] = 0.f;

    const int frow = tid >> 3, fq = tid & 7;
    auto fill = [&](int c) {
        const int kb = c * 32;
        const uint32_t bufb = sb + (uint32_t)((c & 1) * GBUF * 4);
#pragma unroll
        for (int it = 0; it < 4; it++) {
            int row = frow + it * 32;
            cp16(bufb + (uint32_t)((row * GPAD + fq * 4) * 4),
                 X + (size_t)(m0 + row) * cE + kb + fq * 4);
        }
#pragma unroll
        for (int it = 0; it < 2; it++) {
            int row = frow + it * 32;
            cp16(bufb + (uint32_t)((GA_SZ + row * GPAD + fq * 4) * 4),
                 W + (size_t)(n0 + row) * cE + kb + fq * 4);
        }
        cp_commit();
    };

    fill(0);
    for (int c = 0; c < 16; ++c) {
        if (c + 1 < 16) { fill(c + 1); cp_wait1(); }
        else cp_wait0();
        __syncthreads();
        const uint32_t bufb = (uint32_t)((c & 1) * GBUF * 4);
#pragma unroll
        for (int kt = 0; kt < 4; kt++) {
            uint32_t araw[2][4], braw[2][4];
#pragma unroll
            for (int mt = 0; mt < 2; mt++)
                ldmx4(araw[mt], sb + bufb + a_lm +
                                (uint32_t)((mt * 16 * GPAD + kt * 8) * 4));
#pragma unroll
            for (int p = 0; p < 2; p++)
                ldmx4(braw[p], sb + bufb + b_lm +
                               (uint32_t)((p * 16 * GPAD + kt * 8) * 4));
            uint32_t ah[2][4], al[2][4], bh[2][4], bl[2][4];
#pragma unroll
            for (int mt = 0; mt < 2; mt++)
#pragma unroll
                for (int r = 0; r < 4; r++)
                    tf32split(araw[mt][r], ah[mt][r], al[mt][r]);
#pragma unroll
            for (int p = 0; p < 2; p++)
#pragma unroll
                for (int r = 0; r < 4; r++)
                    tf32split(braw[p][r], bh[p][r], bl[p][r]);
#pragma unroll
            for (int mt = 0; mt < 2; mt++)
#pragma unroll
                for (int nt = 0; nt < 4; nt++) {
                    const int p = nt >> 1, w = nt & 1;
                    float* cc = acc[mt][nt];
                    mma8(cc, ah[mt], bh[p][w], bh[p][2 + w]);
                    mma8(cc, ah[mt], bl[p][w], bl[p][2 + w]);
                    mma8(cc, al[mt], bh[p][w], bh[p][2 + w]);
                }
        }
        __syncthreads();
    }

    const int h = blockIdx.y;
#pragma unroll
    for (int mt = 0; mt < 2; mt++) {
        const int m = m0 + warpM * 32 + mt * 16 + (lane >> 2);
        const int b = m >> 11, l = m & (cL - 1);
#pragma unroll
        for (int nt = 0; nt < 4; nt++) {
            const int dcol = warpN * 32 + nt * 8 + (lane & 3) * 2;
            const float2 bb = *(const float2*)(bias + n0 + dcol);
            float2 lo = make_float2(acc[mt][nt][0] + bb.x, acc[mt][nt][1] + bb.y);
            float2 hi = make_float2(acc[mt][nt][2] + bb.x, acc[mt][nt][3] + bb.y);
            if (which == 3) {
                *(float2*)(dst + (size_t)m * cE + n0 + dcol) = lo;
                *(float2*)(dst + (size_t)(m + 8) * cE + n0 + dcol) = hi;
            } else {
                float* G = (which == 0) ? g_Q : (which == 1) ? g_K : g_V;
                float* gp = G + (((size_t)(b * cH + h)) * cL + l) * cD + dcol;
                *(float2*)gp = lo;
                *(float2*)(gp + 8 * cD) = hi;
            }
        }
    }
}

// ---------------------------------------------------------------------------
// Flash attention on tensor cores (mma.sync tf32, plain).
// Block = (b,h) x 64 q-rows, 128 threads / 4 warps, warp = 16 q-rows.
// S = Q K^T via mma; online softmax in accumulator registers; P permuted to
// A-fragments via shuffles (no smem round-trip); O += P V via mma with V
// transposed+tf32-converted in smem.
// ---------------------------------------------------------------------------
#define APITCH 68
#define ATILE (64 * APITCH)          // floats per 64-row tile
#define AVST 0                        // V stage 0
#define AQS ATILE                     // V stage 1, aliased with Qs (prologue)
#define AKS (2 * ATILE)
#define AVT (3 * ATILE)
#define SMEM_ATTN (4 * ATILE * 4)     // 69,632 B -> 3 CTAs/SM

__global__ __launch_bounds__(128, 3)
void attn_kernel(const int* __restrict__ mask)
{
    extern __shared__ __align__(16) float sm[];
    const uint32_t sb = smem_u32(sm);

    const int tid = threadIdx.x;
    const int lane = tid & 31, w = tid >> 5;
    const int g = lane >> 2, t = lane & 3;
    const int q0 = blockIdx.x * 64, bh = blockIdx.y;
    const int b = bh >> 3, h = bh & 7;
    const float* gq = g_Q + (size_t)bh * cL * cD;
    const float* gk = g_K + (size_t)bh * cL * cD;
    const float* gv = g_V + (size_t)bh * cL * cD;
    const size_t mbase = (size_t)b * cL * cL;

    // ldmatrix addressing (b16 x4 trick on fp32 rows, 16 rows x 8 floats)
    const int g2 = lane >> 3, r8 = lane & 7;
    const int row_in = (g2 & 1) * 8 + r8;
    const int coladd = (g2 >> 1) * 4;

    // ---- prologue: cp.async V(0); fill Qs (tf32); extract Q fragments ----
#pragma unroll
    for (int it = 0; it < 8; it++) {
        int idx = tid + it * 128, row = idx >> 4, q = idx & 15;
        cp16(sb + (uint32_t)((AVST + row * APITCH + q * 4) * 4),
             gv + (size_t)row * cD + q * 4);
    }
    cp_commit();
#pragma unroll
    for (int it = 0; it < 8; it++) {
        int idx = tid + it * 128, row = idx >> 4, q = idx & 15;
        float4 v = *(const float4*)(gq + (size_t)(q0 + row) * cD + q * 4);
        v.x = tf32_rn(v.x); v.y = tf32_rn(v.y);
        v.z = tf32_rn(v.z); v.w = tf32_rn(v.w);
        *(float4*)&sm[AQS + row * APITCH + q * 4] = v;
    }
    __syncthreads();
    uint32_t qf[8][4];
    {
        const uint32_t a_base =
            sb + (uint32_t)((AQS + (w * 16 + row_in) * APITCH + coladd) * 4);
#pragma unroll
        for (int ks = 0; ks < 8; ks++) ldmx4(qf[ks], a_base + ks * 32);
    }

    float accO[8][4];
#pragma unroll
    for (int nt = 0; nt < 8; nt++)
#pragma unroll
        for (int r = 0; r < 4; r++) accO[nt][r] = 0.f;
    float m0 = -1e30f, m1 = -1e30f, l0 = 0.f, l1 = 0.f;
    const float RSL = 0.04419417382415922f * 1.44269504088896340f;

    const int* mrow0 = mask + mbase + (size_t)(q0 + w * 16 + g) * cL + 2 * t;
    const int* mrow1 = mrow0 + 8 * cL;
    const uint32_t ks_lm =
        sb + (uint32_t)((AKS + row_in * APITCH + coladd) * 4);
    const uint32_t vt_lm =
        sb + (uint32_t)((AVT + row_in * APITCH + coladd) * 4);

    for (int kt = 0; kt < cL / 64; kt++) {
        const int k0 = kt * 64;
        cp_wait0();            // V(kt) resident in stage kt&1
        __syncthreads();       // prior S/PV reads of Ks/Vt done; V(kt) visible

        // K(kt) fill: LDG -> tf32 -> STS
#pragma unroll
        for (int it = 0; it < 8; it++) {
            int idx = tid + it * 128, row = idx >> 4, q = idx & 15;
            float4 v = *(const float4*)(gk + (size_t)(k0 + row) * cD + q * 4);
            v.x = tf32_rn(v.x); v.y = tf32_rn(v.y);
            v.z = tf32_rn(v.z); v.w = tf32_rn(v.w);
            *(float4*)&sm[AKS + row * APITCH + q * 4] = v;
        }
        // V(kt+1) prefetch
        if (kt + 1 < cL / 64) {
            const uint32_t stg = (uint32_t)(((kt + 1) & 1) ? AQS : AVST);
#pragma unroll
            for (int it = 0; it < 8; it++) {
                int idx = tid + it * 128, row = idx >> 4, q = idx & 15;
                cp16(sb + (stg + (uint32_t)(row * APITCH + q * 4)) * 4,
                     gv + (size_t)(k0 + 64 + row) * cD + q * 4);
            }
        }
        cp_commit();
        // transpose V(kt) -> Vt with tf32 convert (conflict-free mapping)
        {
            const int stg = (kt & 1) ? AQS : AVST;
#pragma unroll
            for (int q = 0; q < 4; q++)
#pragma unroll
                for (int lh = 0; lh < 2; lh++) {
                    int l = lane + lh * 32;
                    int d0 = w * 4 + q * 16;
                    float4 v = *(const float4*)&sm[stg + l * APITCH + d0];
                    sm[AVT + (d0 + 0) * APITCH + l] = tf32_rn(v.x);
                    sm[AVT + (d0 + 1) * APITCH + l] = tf32_rn(v.y);
                    sm[AVT + (d0 + 2) * APITCH + l] = tf32_rn(v.z);
                    sm[AVT + (d0 + 3) * APITCH + l] = tf32_rn(v.w);
                }
        }
        // mask -> bit fields (hide LDG latency behind the barrier)
        uint32_t um0 = 0, um1 = 0;
#pragma unroll
        for (int nt = 0; nt < 8; nt++) {
            int2 a = *(const int2*)(mrow0 + k0 + nt * 8);
            int2 c = *(const int2*)(mrow1 + k0 + nt * 8);
            um0 |= ((a.x != 0) << (nt * 2)) | ((a.y != 0) << (nt * 2 + 1));
            um1 |= ((c.x != 0) << (nt * 2)) | ((c.y != 0) << (nt * 2 + 1));
        }
        __syncthreads();       // Ks, Vt ready

        // ---- S = Q K^T ----
        float accS[8][4];
#pragma unroll
        for (int nt = 0; nt < 8; nt++)
#pragma unroll
            for (int r = 0; r < 4; r++) accS[nt][r] = 0.f;
#pragma unroll
        for (int ks = 0; ks < 8; ks++) {
#pragma unroll
            for (int p = 0; p < 4; p++) {
                uint32_t br[4];
                ldmx4(br, ks_lm + (uint32_t)((p * 16 * APITCH + ks * 8) * 4));
                mma8(accS[2 * p], qf[ks], br[0], br[2]);
                mma8(accS[2 * p + 1], qf[ks], br[1], br[3]);
            }
        }

        // ---- mask + online softmax (raw units, scale folded into exp2) ----
#pragma unroll
        for (int nt = 0; nt < 8; nt++) {
            accS[nt][0] = ((um0 >> (nt * 2)) & 1) ? accS[nt][0] : -1e20f;
            accS[nt][1] = ((um0 >> (nt * 2 + 1)) & 1) ? accS[nt][1] : -1e20f;
            accS[nt][2] = ((um1 >> (nt * 2)) & 1) ? accS[nt][2] : -1e20f;
            accS[nt][3] = ((um1 >> (nt * 2 + 1)) & 1) ? accS[nt][3] : -1e20f;
        }
        float mx0 = -1e30f, mx1 = -1e30f;
#pragma unroll
        for (int nt = 0; nt < 8; nt++) {
            mx0 = fmaxf(mx0, fmaxf(accS[nt][0], accS[nt][1]));
            mx1 = fmaxf(mx1, fmaxf(accS[nt][2], accS[nt][3]));
        }
        mx0 = fmaxf(mx0, __shfl_xor_sync(0xffffffffu, mx0, 1));
        mx0 = fmaxf(mx0, __shfl_xor_sync(0xffffffffu, mx0, 2));
        mx1 = fmaxf(mx1, __shfl_xor_sync(0xffffffffu, mx1, 1));
        mx1 = fmaxf(mx1, __shfl_xor_sync(0xffffffffu, mx1, 2));
        const float m0n = fmaxf(m0, mx0), m1n = fmaxf(m1, mx1);
        const float fac0 = ex2((m0 - m0n) * RSL), fac1 = ex2((m1 - m1n) * RSL);
        m0 = m0n; m1 = m1n;
        float s0 = 0.f, s1 = 0.f;
#pragma unroll
        for (int nt = 0; nt < 8; nt++) {
            accS[nt][0] = ex2((accS[nt][0] - m0n) * RSL);
            accS[nt][1] = ex2((accS[nt][1] - m0n) * RSL);
            accS[nt][2] = ex2((accS[nt][2] - m1n) * RSL);
            accS[nt][3] = ex2((accS[nt][3] - m1n) * RSL);
            s0 += accS[nt][0] + accS[nt][1];
            s1 += accS[nt][2] + accS[nt][3];
        }
        s0 += __shfl_xor_sync(0xffffffffu, s0, 1);
        s0 += __shfl_xor_sync(0xffffffffu, s0, 2);
        s1 += __shfl_xor_sync(0xffffffffu, s1, 1);
        s1 += __shfl_xor_sync(0xffffffffu, s1, 2);
        l0 = l0 * fac0 + s0;
        l1 = l1 * fac1 + s1;
#pragma unroll
        for (int nt = 0; nt < 8; nt++) {
            accO[nt][0] *= fac0; accO[nt][1] *= fac0;
            accO[nt][2] *= fac1; accO[nt][3] *= fac1;
        }

        // ---- O += P V : A-fragments from accS via shuffles ----
        const int base = lane & 28;
        const int sA = base + (t >> 1), sB = sA + 2;
#pragma unroll
        for (int j = 0; j < 8; j++) {
            uint32_t u0 = __float_as_uint(tf32_rn(accS[j][0]));
            uint32_t u1 = __float_as_uint(tf32_rn(accS[j][1]));
            uint32_t u2 = __float_as_uint(tf32_rn(accS[j][2]));
            uint32_t u3 = __float_as_uint(tf32_rn(accS[j][3]));
            uint32_t a[4];
            uint32_t e, o;
            e = __shfl_sync(0xffffffffu, u0, sA);
            o = __shfl_sync(0xffffffffu, u1, sA);
            a[0] = (t & 1) ? o : e;
            e = __shfl_sync(0xffffffffu, u2, sA);
            o = __shfl_sync(0xffffffffu, u3, sA);
            a[1] = (t & 1) ? o : e;
            e = __shfl_sync(0xffffffffu, u0, sB);
            o = __shfl_sync(0xffffffffu, u1, sB);
            a[2] = (t & 1) ? o : e;
            e = __shfl_sync(0xffffffffu, u2, sB);
            o = __shfl_sync(0xffffffffu, u3, sB);
            a[3] = (t & 1) ? o : e;
#pragma unroll
            for (int p = 0; p < 4; p++) {
                uint32_t br[4];
                ldmx4(br, vt_lm + (uint32_t)((p * 16 * APITCH + j * 8) * 4));
                mma8(accO[2 * p], a, br[0], br[2]);
                mma8(accO[2 * p + 1], a, br[1], br[3]);
            }
        }
    }

    // ---- epilogue: normalize, write [B, L, E] ----
    const float inv0 = 1.0f / l0, inv1 = 1.0f / l1;
    const int r0 = q0 + w * 16 + g;
    float* ob0 = g_O + ((size_t)(b * cL + r0)) * cE + h * cD;
    float* ob1 = ob0 + (size_t)8 * cE;
#pragma unroll
    for (int nt = 0; nt < 8; nt++) {
        const int dcol = nt * 8 + 2 * t;
        *(float2*)(ob0 + dcol) =
            make_float2(accO[nt][0] * inv0, accO[nt][1] * inv0);
        *(float2*)(ob1 + dcol) =
            make_float2(accO[nt][2] * inv1, accO[nt][3] * inv1);
    }
}

// ---------------------------------------------------------------------------
extern "C" void kernel_launch(void* const* d_in, const int* in_sizes, int n_in,
                              void* d_out, int out_size)
{
    (void)in_sizes; (void)n_in; (void)out_size;
    const float* values = (const float*)d_in[0];
    const float* keys   = (const float*)d_in[1];
    const float* query  = (const float*)d_in[2];
    const int*   mask   = (const int*)d_in[3];
    const float* Wv = (const float*)d_in[4];
    const float* bv = (const float*)d_in[5];
    const float* Wk = (const float*)d_in[6];
    const float* bk = (const float*)d_in[7];
    const float* Wq = (const float*)d_in[8];
    const float* bq = (const float*)d_in[9];
    const float* Wo = (const float*)d_in[10];
    const float* bo = (const float*)d_in[11];
    float* out = (float*)d_out;

    cudaFuncSetAttribute(gemm_tc, cudaFuncAttributeMaxDynamicSharedMemorySize,
                         GSMEM);
    cudaFuncSetAttribute(attn_kernel, cudaFuncAttributeMaxDynamicSharedMemorySize,
                         SMEM_ATTN);

    const dim3 gg((cB * cL) / 128, cE / 64);   // (32, 8)
    gemm_tc<<<gg, 256, GSMEM>>>(query,  Wq, bq, nullptr, 0);
    gemm_tc<<<gg, 256, GSMEM>>>(keys,   Wk, bk, nullptr, 1);
    gemm_tc<<<gg, 256, GSMEM>>>(values, Wv, bv, nullptr, 2);

    attn_kernel<<<dim3(cL / 64, cB * cH), 128, SMEM_ATTN>>>(mask);

    gemm_tc<<<gg, 256, GSMEM>>>(nullptr, Wo, bo, out, 3);
}